// round 7
// baseline (speedup 1.0000x reference)
#include <cuda_runtime.h>

// MBTR + analytic divergence, GB300 (sm_103a). Round 6:
//   R3 execution shape (384 thr, 256 blocks, 2 g/thread, smem mbtr reduction)
//   + hoisted {gsq, -u} pair table
//   + ex2.approx.ftz.f32 inline PTX (single MUFU; exp2f/libdevice was the R5 trap)
//   + software-pipelined table reads (prefetch next pair during compute)
//   + self-pair stored as zero row -> uniform 48-row segments, no edge cases
//
// Pair (i,j): d=|ri-rj|, gf=1/d, wf=exp(-d), u=(ri-rj)/d, gfs=gf/sigma
//   tt=(g-gf)/sigma, gv=C*exp(-tt^2/2), C=dx/(sqrt(2pi)*sigma)
//   mbtr[b,zi,zj,g] += wf*gv
//   div at atom a from partner j (both orientations): -s*u_aj,
//     s = wf*gv*(1 + (gf^2/sigma)*tt)
// Slot (e1,e2) at atom a: (e1==za)*acc[e2] + (e2==za)*acc[e1].

#define NB     32
#define NA     48
#define NE     4
#define NG     128
#define GPB    16
#define LAYERS 8
#define NCHUNK (NG / GPB)      // 8
#define NTHR   (NA * LAYERS)   // 384

#define DIV_SLOT_STRIDE (NG * NA * 3)
#define DIV_G_STRIDE    (NA * 3)

static __device__ __forceinline__ float ex2f(float x) {
    float y;
    asm("ex2.approx.ftz.f32 %0, %1;" : "=f"(y) : "f"(x));
    return y;
}

__global__ void __launch_bounds__(NTHR, 2)
mbtr_kernel(const float* __restrict__ r,
            const int*   __restrict__ z,
            const float* __restrict__ grid,
            float*       __restrict__ out)
{
    const int b  = blockIdx.x / NCHUNK;
    const int gc = blockIdx.x - b * NCHUNK;
    const int t  = threadIdx.x;
    const int a  = t % NA;
    const int l  = t / NA;
    const int g0 = gc * GPB + l;
    const int g1 = g0 + LAYERS;

    __shared__ float4 tabA[NA][NA];      // {gfs, wf*C, gsq, -ux}
    __shared__ float2 tabB[NA][NA];      // {-uy, -uz}
    __shared__ float4 rs[NA];
    __shared__ int    zs[NA], S[NA], segs[NE + 1];
    __shared__ float  sm_mbtr[NE * NE][GPB];

    const float INV_SIGMA = 20.0f;
    const float CM        = -0.72134752044448170f;   // -0.5 * log2(e)

    if (t < NA) {
        zs[t] = z[t];
        const float* rp = r + (b * NA + t) * 3;
        rs[t] = make_float4(rp[0], rp[1], rp[2], 0.f);
    }
    if (t < NE * NE * GPB) sm_mbtr[t / GPB][t % GPB] = 0.f;
    __syncthreads();

    // Counting-sort all 48 atoms (incl. self; self-row zeroed in the table).
    if (t == 0) {
        int cnt[NE] = {0, 0, 0, 0};
        for (int j = 0; j < NA; j++) cnt[zs[j]]++;
        int off = 0, pos[NE];
        segs[0] = 0;
        #pragma unroll
        for (int e = 0; e < NE; e++) { pos[e] = off; off += cnt[e]; segs[e + 1] = off; }
        for (int j = 0; j < NA; j++) S[pos[zs[j]]++] = j;
    }
    __syncthreads();

    // Pair-table fill: 2304 entries over 384 threads (6 each).
    {
        const float gdx = grid[1] - grid[0];
        const float C   = gdx * 0.3989422804014327f * INV_SIGMA;
        #pragma unroll
        for (int it = 0; it < (NA * NA) / NTHR; it++) {
            const int idx = it * NTHR + t;
            const int jp = idx / NA;
            const int a2 = idx - jp * NA;
            const int p  = S[jp];
            if (p == a2) {
                tabA[jp][a2] = make_float4(0.f, 0.f, 0.f, 0.f);
                tabB[jp][a2] = make_float2(0.f, 0.f);
            } else {
                const float4 ra = rs[a2], rp = rs[p];
                const float dx = ra.x - rp.x, dy = ra.y - rp.y, dz = ra.z - rp.z;
                const float d2   = fmaf(dx, dx, fmaf(dy, dy, dz * dz));
                const float invd = rsqrtf(d2);
                const float d    = d2 * invd;
                const float wf   = __expf(-d);
                tabA[jp][a2] = make_float4(invd * INV_SIGMA, wf * C,
                                           invd * invd * INV_SIGMA, -dx * invd);
                tabB[jp][a2] = make_float2(-dy * invd, -dz * invd);
            }
        }
    }
    __syncthreads();

    const int   za  = zs[a];
    const float gg0 = grid[g0] * INV_SIGMA;
    const float gg1 = grid[g1] * INV_SIGMA;

    float* __restrict__ dout = out + (NB * NE * NE * NG);
    float* const p0 = dout + ((size_t)b * NE * NE * NG + g0) * DIV_G_STRIDE + a * 3;
    float* const p1 = p0 + LAYERS * DIV_G_STRIDE;

    #pragma unroll
    for (int e = 0; e < NE; e++) {
        float w0 = 0.f, x0 = 0.f, y0 = 0.f, z0 = 0.f;
        float w1 = 0.f, x1 = 0.f, y1 = 0.f, z1 = 0.f;
        const int j0 = segs[e], j1e = segs[e + 1];

        // Software-pipelined: table entry for iteration jp is loaded during
        // iteration jp-1's compute (LDS 29 cyc overlapped with exp chain).
        float4 A  = tabA[j0][a];
        float2 Bv = tabB[j0][a];
        for (int jp = j0; jp < j1e; jp++) {
            const int jn = (jp + 1 < j1e) ? jp + 1 : jp;
            const float4 An = tabA[jn][a];
            const float2 Bn = tabB[jn][a];

            const float t0 = gg0 - A.x;
            const float t1 = gg1 - A.x;
            const float E0 = ex2f((CM * t0) * t0);
            const float E1 = ex2f((CM * t1) * t1);
            const float wg0 = A.y * E0;
            const float wg1 = A.y * E1;
            const float s0  = fmaf(wg0 * A.z, t0, wg0);
            const float s1  = fmaf(wg1 * A.z, t1, wg1);
            w0 += wg0;               w1 += wg1;
            x0 = fmaf(s0, A.w,  x0); x1 = fmaf(s1, A.w,  x1);
            y0 = fmaf(s0, Bv.x, y0); y1 = fmaf(s1, Bv.x, y1);
            z0 = fmaf(s0, Bv.y, z0); z1 = fmaf(s1, Bv.y, z1);

            A = An; Bv = Bn;
        }

        // mbtr partial sums (block-local shared reduction).
        atomicAdd(&sm_mbtr[za * NE + e][l],          w0);
        atomicAdd(&sm_mbtr[za * NE + e][l + LAYERS], w1);

        // Nonzero div slots for this segment.
        if (e == za) {
            float* q0 = p0 + (za * NE + za) * DIV_SLOT_STRIDE;
            float* q1 = p1 + (za * NE + za) * DIV_SLOT_STRIDE;
            q0[0] = 2.f * x0; q0[1] = 2.f * y0; q0[2] = 2.f * z0;
            q1[0] = 2.f * x1; q1[1] = 2.f * y1; q1[2] = 2.f * z1;
        } else {
            float* q0 = p0 + (za * NE + e) * DIV_SLOT_STRIDE;
            float* q1 = p1 + (za * NE + e) * DIV_SLOT_STRIDE;
            q0[0] = x0; q0[1] = y0; q0[2] = z0;
            q1[0] = x1; q1[1] = y1; q1[2] = z1;
            q0 = p0 + (e * NE + za) * DIV_SLOT_STRIDE;
            q1 = p1 + (e * NE + za) * DIV_SLOT_STRIDE;
            q0[0] = x0; q0[1] = y0; q0[2] = z0;
            q1[0] = x1; q1[1] = y1; q1[2] = z1;
        }
    }

    // Zero slots (za not involved): dependency-free epilogue.
    #pragma unroll
    for (int e1 = 0; e1 < NE; e1++) {
        #pragma unroll
        for (int e2 = 0; e2 < NE; e2++) {
            if (e1 != za && e2 != za) {
                float* q0 = p0 + (e1 * NE + e2) * DIV_SLOT_STRIDE;
                float* q1 = p1 + (e1 * NE + e2) * DIV_SLOT_STRIDE;
                q0[0] = 0.f; q0[1] = 0.f; q0[2] = 0.f;
                q1[0] = 0.f; q1[1] = 0.f; q1[2] = 0.f;
            }
        }
    }

    // mbtr: exclusive rows for this block.
    __syncthreads();
    if (t < NE * NE * GPB) {
        const int slot = t / GPB, gtt = t - slot * GPB;
        out[((size_t)b * NE * NE + slot) * NG + gc * GPB + gtt] = sm_mbtr[slot][gtt];
    }
}

extern "C" void kernel_launch(void* const* d_in, const int* in_sizes, int n_in,
                              void* d_out, int out_size)
{
    const float* r    = (const float*)d_in[0];
    const int*   z    = (const int*)  d_in[1];
    const float* grid = (const float*)d_in[2];
    float*       out  = (float*)d_out;

    mbtr_kernel<<<NB * NCHUNK, NTHR>>>(r, z, grid, out);
}

// round 8
// speedup vs baseline: 1.4059x; 1.4059x over previous
#include <cuda_runtime.h>

// MBTR + analytic divergence, GB300 (sm_103a). Round 7: lanes = grid points.
//
// Block = (b, g-chunk of 32, atom-third of 16). Warp = one atom, lane = one g.
// Band skip: gaussian center gfs=gf/sigma; pair is irrelevant to this warp's
// 32-g window unless gfs in [gg_lo-6.5, gg_hi+6.5] (error < 1e-9 absolute).
// Predicate is warp-uniform -> 48-bit mask via 2 ballots, iterate set bits.
// Table reads are warp-uniform LDS broadcasts. Div stores transposed through
// padded smem so global writes are dense 192B rows. mbtr via coalesced global
// atomicAdd into a pre-zeroed region (separate tiny kernel, same stream).
//
// Pair (i,j): d=|ri-rj|, gf=1/d, wf=exp(-d), u=(ri-rj)/d
//   tt=(g-gf)/sigma, gv=C*exp(-tt^2/2), C=dx/(sqrt(2pi)*sigma)
//   mbtr[b,zi,zj,g] += wf*gv
//   div at atom a from partner j (both orientations): -s*u_aj,
//     s = wf*gv*(1 + (gf^2/sigma)*tt)
// Slot (e1,e2) at atom a: (e1==za)*acc[e2] + (e2==za)*acc[e1].

#define NB   32
#define NA   48
#define NE   4
#define NG   128
#define ATH  16                 // atoms per block
#define GC   32                 // grid points per block
#define NTHR (ATH * GC)         // 512
#define NTHIRD (NA / ATH)       // 3
#define NGCH   (NG / GC)        // 4
#define NBLK (NB * NGCH * NTHIRD)   // 384
#define MBTR_SZ (NB * NE * NE * NG) // 65536
#define ROWQ (ATH * 3)          // 48 floats per (slot,g) row owned by block
#define ACCPAD (ROWQ + 1)       // 49: pad so g-strided STS is conflict-free

static __device__ __forceinline__ float ex2f(float x) {
    float y;
    asm("ex2.approx.ftz.f32 %0, %1;" : "=f"(y) : "f"(x));
    return y;
}

__global__ void zero_mbtr(float* __restrict__ out) {
    out[blockIdx.x * 1024 + threadIdx.x] = 0.f;   // 64 x 1024 = 65536
}

__global__ void __launch_bounds__(NTHR, 2)
mbtr_kernel(const float* __restrict__ r,
            const int*   __restrict__ z,
            const float* __restrict__ grid,
            float*       __restrict__ out)
{
    const int bid    = blockIdx.x;
    const int third  = bid % NTHIRD;
    const int tmp    = bid / NTHIRD;
    const int gchunk = tmp % NGCH;
    const int b      = tmp / NGCH;

    const int t    = threadIdx.x;
    const int al   = t >> 5;            // warp id = local atom
    const int lane = t & 31;
    const int a    = third * ATH + al;  // global atom
    const int g    = gchunk * GC + lane;

    __shared__ float4 tabA[NA][ATH];    // {gfs, wf*C, gsq, -ux}
    __shared__ float2 tabB[NA][ATH];    // {-uy, -uz}
    __shared__ float  gfsT[ATH][NA];    // gfs, lane-major readable
    __shared__ float  acc[NE][GC][ACCPAD];
    __shared__ float4 rs[NA];
    __shared__ int    zs[NA], S[NA], segs[NE + 1];

    const float INV_SIGMA = 20.0f;
    const float CM        = -0.72134752044448170f;   // -0.5 * log2(e)
    const float BAND      = 6.5f;                    // sigma units

    if (t < NA) {
        zs[t] = z[t];
        const float* rp = r + (b * NA + t) * 3;
        rs[t] = make_float4(rp[0], rp[1], rp[2], 0.f);
    }
    __syncthreads();

    if (t == 0) {
        int cnt[NE] = {0, 0, 0, 0};
        for (int j = 0; j < NA; j++) cnt[zs[j]]++;
        int off = 0, pos[NE];
        segs[0] = 0;
        #pragma unroll
        for (int e = 0; e < NE; e++) { pos[e] = off; off += cnt[e]; segs[e + 1] = off; }
        for (int j = 0; j < NA; j++) S[pos[zs[j]]++] = j;
    }
    __syncthreads();

    // Pair table: 48 partners x 16 local atoms = 768 entries over 512 threads.
    {
        const float gdx = grid[1] - grid[0];
        const float C   = gdx * 0.3989422804014327f * INV_SIGMA;
        for (int f = t; f < NA * ATH; f += NTHR) {
            const int jp  = f >> 4;
            const int al2 = f & (ATH - 1);
            const int a2  = third * ATH + al2;
            const int p   = S[jp];
            if (p == a2) {
                tabA[jp][al2] = make_float4(0.f, 0.f, 0.f, 0.f);
                tabB[jp][al2] = make_float2(0.f, 0.f);
                gfsT[al2][jp] = 0.f;
            } else {
                const float4 ra = rs[a2], rp = rs[p];
                const float dx = ra.x - rp.x, dy = ra.y - rp.y, dz = ra.z - rp.z;
                const float d2   = fmaf(dx, dx, fmaf(dy, dy, dz * dz));
                const float invd = rsqrtf(d2);
                const float d    = d2 * invd;
                const float wf   = __expf(-d);
                const float gfs  = invd * INV_SIGMA;
                tabA[jp][al2] = make_float4(gfs, wf * C,
                                            invd * invd * INV_SIGMA, -dx * invd);
                tabB[jp][al2] = make_float2(-dy * invd, -dz * invd);
                gfsT[al2][jp] = gfs;
            }
        }
    }
    __syncthreads();

    const int   za = zs[a];
    const float gg = grid[g] * INV_SIGMA;
    const float bandlo = __shfl_sync(0xffffffffu, gg, 0)  - BAND;
    const float bandhi = __shfl_sync(0xffffffffu, gg, 31) + BAND;

    // 48-bit active-pair mask (warp-uniform).
    const float f0 = gfsT[al][lane];
    const unsigned m0 = __ballot_sync(0xffffffffu, f0 > bandlo && f0 < bandhi);
    const float f1 = (lane < 16) ? gfsT[al][32 + lane] : 0.f;
    const unsigned m1 = __ballot_sync(0xffffffffu,
                                      lane < 16 && f1 > bandlo && f1 < bandhi);
    const unsigned long long mask =
        (unsigned long long)m0 | ((unsigned long long)(m1 & 0xFFFFu) << 32);

    #pragma unroll
    for (int e = 0; e < NE; e++) {
        const unsigned long long segm =
            mask & ((1ull << segs[e + 1]) - (1ull << segs[e]));
        float wv = 0.f, xv = 0.f, yv = 0.f, zv = 0.f;
        unsigned long long m = segm;
        while (m) {
            const int jp = __ffsll((long long)m) - 1;
            m &= m - 1;
            const float4 A  = tabA[jp][al];     // broadcast LDS
            const float2 Bv = tabB[jp][al];
            const float tt = gg - A.x;
            const float E  = ex2f((CM * tt) * tt);
            const float wg = A.y * E;
            const float s  = fmaf(wg * A.z, tt, wg);
            wv += wg;
            xv = fmaf(s, A.w,  xv);
            yv = fmaf(s, Bv.x, yv);
            zv = fmaf(s, Bv.y, zv);
        }
        // mbtr: coalesced 128B RED.ADD per warp per segment.
        atomicAdd(&out[(((b * NE + za) * NE + e) * NG) + g], wv);
        // stash for transposed store
        acc[e][lane][al * 3 + 0] = xv;
        acc[e][lane][al * 3 + 1] = yv;
        acc[e][lane][al * 3 + 2] = zv;
    }
    __syncthreads();

    // Transposed div store: 16 slots x 32 g x 48 floats = 24576 per block.
    // Thread handles 3 fixed (g,q) cells per slot -> dense 192B rows.
    int gq[3], qq[3], zaq[3];
    #pragma unroll
    for (int k = 0; k < 3; k++) {
        const int f = k * NTHR + t;
        gq[k]  = f / ROWQ;
        qq[k]  = f - gq[k] * ROWQ;
        zaq[k] = zs[third * ATH + qq[k] / 3];
    }
    float* __restrict__ dbase = out + MBTR_SZ
        + ((size_t)(b * NE * NE) * NG + gchunk * GC) * (NA * 3)
        + third * ROWQ;

    #pragma unroll
    for (int slot = 0; slot < NE * NE; slot++) {
        const int e1 = slot >> 2, e2 = slot & 3;
        #pragma unroll
        for (int k = 0; k < 3; k++) {
            float v = 0.f;
            if (zaq[k] == e1) v += acc[e2][gq[k]][qq[k]];
            if (zaq[k] == e2) v += acc[e1][gq[k]][qq[k]];
            dbase[(size_t)slot * (NG * NA * 3) + gq[k] * (NA * 3) + qq[k]] = v;
        }
    }
}

extern "C" void kernel_launch(void* const* d_in, const int* in_sizes, int n_in,
                              void* d_out, int out_size)
{
    const float* r    = (const float*)d_in[0];
    const int*   z    = (const int*)  d_in[1];
    const float* grid = (const float*)d_in[2];
    float*       out  = (float*)d_out;

    zero_mbtr<<<MBTR_SZ / 1024, 1024>>>(out);
    mbtr_kernel<<<NBLK, NTHR>>>(r, z, grid, out);
}

// round 10
// speedup vs baseline: 1.4863x; 1.0572x over previous
#include <cuda_runtime.h>

// MBTR + analytic divergence, GB300 (sm_103a). Round 8 = R7 with better
// chip-filling geometry:
//   ATH 16->8 (256-thread blocks, 768 blocks): wave tail 14%->4%,
//   4 blocks/SM residency; BAND 6.5->6.0.
//
// Block = (b, g-chunk of 32, atom-sixth of 8). Warp = one atom, lane = one g.
// Band skip: pair irrelevant to warp's 32-g window unless gfs in
// [gg_lo-6, gg_hi+6] sigma (dropped tail < 2e-8 per pair). Warp-uniform
// predicate -> 48-bit mask via 2 ballots, iterate set bits. Table reads are
// warp-uniform LDS broadcasts. Div stores transposed through padded smem so
// global writes are dense. mbtr via coalesced global atomicAdd into a
// pre-zeroed region (tiny zero kernel first).

#define NB   32
#define NA   48
#define NE   4
#define NG   128
#define ATH  8                  // atoms per block
#define GC   32                 // grid points per block
#define NTHR (ATH * GC)         // 256
#define NTHIRD (NA / ATH)       // 6
#define NGCH   (NG / GC)        // 4
#define NBLK (NB * NGCH * NTHIRD)   // 768
#define MBTR_SZ (NB * NE * NE * NG) // 65536
#define ROWQ (ATH * 3)          // 24 floats per (slot,g) row owned by block
#define ACCPAD (ROWQ + 1)       // 25: pad so g-strided STS is conflict-free

static __device__ __forceinline__ float ex2f(float x) {
    float y;
    asm("ex2.approx.ftz.f32 %0, %1;" : "=f"(y) : "f"(x));
    return y;
}

__global__ void zero_mbtr(float* __restrict__ out) {
    out[blockIdx.x * 1024 + threadIdx.x] = 0.f;   // 64 x 1024 = 65536
}

__global__ void __launch_bounds__(NTHR, 4)
mbtr_kernel(const float* __restrict__ r,
            const int*   __restrict__ z,
            const float* __restrict__ grid,
            float*       __restrict__ out)
{
    const int bid    = blockIdx.x;
    const int third  = bid % NTHIRD;
    const int tmp    = bid / NTHIRD;
    const int gchunk = tmp % NGCH;
    const int b      = tmp / NGCH;

    const int t    = threadIdx.x;
    const int al   = t >> 5;            // warp id = local atom
    const int lane = t & 31;
    const int a    = third * ATH + al;  // global atom
    const int g    = gchunk * GC + lane;

    __shared__ float4 tabA[NA][ATH];    // {gfs, wf*C, gsq, -ux}
    __shared__ float2 tabB[NA][ATH];    // {-uy, -uz}
    __shared__ float  gfsT[ATH][NA];    // gfs, lane-major readable
    __shared__ float  acc[NE][GC][ACCPAD];
    __shared__ float4 rs[NA];
    __shared__ int    zs[NA], S[NA], segs[NE + 1];

    const float INV_SIGMA = 20.0f;
    const float CM        = -0.72134752044448170f;   // -0.5 * log2(e)
    const float BAND      = 6.0f;                    // sigma units

    if (t < NA) {
        zs[t] = z[t];
        const float* rp = r + (b * NA + t) * 3;
        rs[t] = make_float4(rp[0], rp[1], rp[2], 0.f);
    }
    __syncthreads();

    if (t == 0) {
        int cnt[NE] = {0, 0, 0, 0};
        for (int j = 0; j < NA; j++) cnt[zs[j]]++;
        int off = 0, pos[NE];
        segs[0] = 0;
        #pragma unroll
        for (int e = 0; e < NE; e++) { pos[e] = off; off += cnt[e]; segs[e + 1] = off; }
        for (int j = 0; j < NA; j++) S[pos[zs[j]]++] = j;
    }
    __syncthreads();

    // Pair table: 48 partners x 8 local atoms = 384 entries over 256 threads.
    {
        const float gdx = grid[1] - grid[0];
        const float C   = gdx * 0.3989422804014327f * INV_SIGMA;
        for (int f = t; f < NA * ATH; f += NTHR) {
            const int jp  = f >> 3;
            const int al2 = f & (ATH - 1);
            const int a2  = third * ATH + al2;
            const int p   = S[jp];
            if (p == a2) {
                tabA[jp][al2] = make_float4(0.f, 0.f, 0.f, 0.f);
                tabB[jp][al2] = make_float2(0.f, 0.f);
                gfsT[al2][jp] = 0.f;
            } else {
                const float4 ra = rs[a2], rp = rs[p];
                const float dx = ra.x - rp.x, dy = ra.y - rp.y, dz = ra.z - rp.z;
                const float d2   = fmaf(dx, dx, fmaf(dy, dy, dz * dz));
                const float invd = rsqrtf(d2);
                const float d    = d2 * invd;
                const float wf   = __expf(-d);
                const float gfs  = invd * INV_SIGMA;
                tabA[jp][al2] = make_float4(gfs, wf * C,
                                            invd * invd * INV_SIGMA, -dx * invd);
                tabB[jp][al2] = make_float2(-dy * invd, -dz * invd);
                gfsT[al2][jp] = gfs;
            }
        }
    }
    __syncthreads();

    const int   za = zs[a];
    const float gg = grid[g] * INV_SIGMA;
    const float bandlo = __shfl_sync(0xffffffffu, gg, 0)  - BAND;
    const float bandhi = __shfl_sync(0xffffffffu, gg, 31) + BAND;

    // 48-bit active-pair mask (warp-uniform).
    const float f0 = gfsT[al][lane];
    const unsigned m0 = __ballot_sync(0xffffffffu, f0 > bandlo && f0 < bandhi);
    const float f1 = (lane < 16) ? gfsT[al][32 + lane] : 0.f;
    const unsigned m1 = __ballot_sync(0xffffffffu,
                                      lane < 16 && f1 > bandlo && f1 < bandhi);
    const unsigned long long mask =
        (unsigned long long)m0 | ((unsigned long long)(m1 & 0xFFFFu) << 32);

    float* const mb = out + (((b * NE + za) * NE) * NG) + g;

    #pragma unroll
    for (int e = 0; e < NE; e++) {
        const unsigned long long segm =
            mask & ((1ull << segs[e + 1]) - (1ull << segs[e]));
        float wv = 0.f, xv = 0.f, yv = 0.f, zv = 0.f;
        unsigned long long m = segm;
        while (m) {
            const int jp = __ffsll((long long)m) - 1;
            m &= m - 1;
            const float4 A  = tabA[jp][al];     // broadcast LDS
            const float2 Bv = tabB[jp][al];
            const float tt = gg - A.x;
            const float E  = ex2f((CM * tt) * tt);
            const float wg = A.y * E;
            const float s  = fmaf(wg * A.z, tt, wg);
            wv += wg;
            xv = fmaf(s, A.w,  xv);
            yv = fmaf(s, Bv.x, yv);
            zv = fmaf(s, Bv.y, zv);
        }
        // mbtr: coalesced 128B RED.ADD per warp per segment.
        atomicAdd(mb + e * NG, wv);
        // stash for transposed store
        acc[e][lane][al * 3 + 0] = xv;
        acc[e][lane][al * 3 + 1] = yv;
        acc[e][lane][al * 3 + 2] = zv;
    }
    __syncthreads();

    // Transposed div store: 16 slots x 32 g x 24 floats = 12288 per block.
    // Thread handles 3 fixed (g,q) cells per slot -> dense rows.
    int gq[3], qq[3], zaq[3];
    #pragma unroll
    for (int k = 0; k < 3; k++) {
        const int f = k * NTHR + t;
        gq[k]  = f / ROWQ;
        qq[k]  = f - gq[k] * ROWQ;
        zaq[k] = zs[third * ATH + qq[k] / 3];
    }
    float* __restrict__ dbase = out + MBTR_SZ
        + ((size_t)(b * NE * NE) * NG + gchunk * GC) * (NA * 3)
        + third * ROWQ;

    #pragma unroll
    for (int slot = 0; slot < NE * NE; slot++) {
        const int e1 = slot >> 2, e2 = slot & 3;
        #pragma unroll
        for (int k = 0; k < 3; k++) {
            float v = 0.f;
            if (zaq[k] == e1) v += acc[e2][gq[k]][qq[k]];
            if (zaq[k] == e2) v += acc[e1][gq[k]][qq[k]];
            dbase[(size_t)slot * (NG * NA * 3) + gq[k] * (NA * 3) + qq[k]] = v;
        }
    }
}

extern "C" void kernel_launch(void* const* d_in, const int* in_sizes, int n_in,
                              void* d_out, int out_size)
{
    const float* r    = (const float*)d_in[0];
    const int*   z    = (const int*)  d_in[1];
    const float* grid = (const float*)d_in[2];
    float*       out  = (float*)d_out;

    zero_mbtr<<<MBTR_SZ / 1024, 1024>>>(out);
    mbtr_kernel<<<NBLK, NTHR>>>(r, z, grid, out);
}